// round 11
// baseline (speedup 1.0000x reference)
#include <cuda_runtime.h>
#include <cuda_fp16.h>
#include <math.h>
#include <stdint.h>

// ---------------------------------------------------------------------------
// MSDeformableAttention — GB300 (plain sm_103 target: tcgen05 unavailable,
// legacy mma.sync tf32 tensor path, ldmatrix fragment loads)
//
//   1) tf32_gemm: v    = value @ vp_w + vp_b            -> V [B*LV, 256] fp16
//   2) tf32_gemm: soaw = query @ [so_w | aw_w] + bias   -> SOAW [B*LQ, 384]
//   3) sample: in-warp softmax + bilinear gather (fp16 V) -> ACC [B*LQ, 256]
//   4) tf32_gemm: out = ACC @ op_w + op_b
//
// B=8, LQ=1024, LV=13294, D=256, H=8, HD=32, L=4, P=4
// levels (h=w,start): (100,0) (50,10000) (25,12500) (13,13125)
// ---------------------------------------------------------------------------

namespace cfg {
constexpr int B  = 8;
constexpr int LQ = 1024;
constexpr int LV = 13294;
constexpr int D  = 256;
constexpr int H  = 8;

constexpr size_t SZ_V_H  = (size_t)B * LV * D;      // 27,226,112 halfs
constexpr size_t SZ_V_F  = (SZ_V_H + 1) / 2;        // in floats
constexpr size_t SZ_SOAW = (size_t)B * LQ * 384;
constexpr size_t SZ_ACC  = (size_t)B * LQ * D;

constexpr size_t OFF_V    = 0;                       // half region
constexpr size_t OFF_SOAW = OFF_V    + SZ_V_F;
constexpr size_t OFF_ACC  = OFF_SOAW + SZ_SOAW;
constexpr size_t SZ_TOT   = OFF_ACC  + SZ_ACC;       // ~18.9M floats (~76 MB)
}  // namespace cfg

__device__ float g_scratch[cfg::SZ_TOT];

// ---------------------------------------------------------------------------
__device__ __forceinline__ uint32_t f2tf32(float x) {
    uint32_t u;
    asm("cvt.rna.tf32.f32 %0, %1;" : "=r"(u) : "f"(x));
    return u;
}

__device__ __forceinline__ void mma_tf32(float d[4], const uint32_t a[4],
                                         const uint32_t b[2]) {
    asm volatile(
        "mma.sync.aligned.m16n8k8.row.col.f32.tf32.tf32.f32 "
        "{%0,%1,%2,%3}, {%4,%5,%6,%7}, {%8,%9}, {%0,%1,%2,%3};"
        : "+f"(d[0]), "+f"(d[1]), "+f"(d[2]), "+f"(d[3])
        : "r"(a[0]), "r"(a[1]), "r"(a[2]), "r"(a[3]), "r"(b[0]), "r"(b[1]));
}

__device__ __forceinline__ void ldsm_x4(uint32_t& r0, uint32_t& r1,
                                        uint32_t& r2, uint32_t& r3,
                                        uint32_t saddr) {
    asm volatile(
        "ldmatrix.sync.aligned.m8n8.x4.shared.b16 {%0,%1,%2,%3}, [%4];"
        : "=r"(r0), "=r"(r1), "=r"(r2), "=r"(r3) : "r"(saddr));
}

// Epilogue pair-store helpers (fp32 or fp16 output)
__device__ __forceinline__ void store_pair(float* C, size_t off,
                                           float v0, float v1) {
    *(float2*)(C + off) = make_float2(v0, v1);
}
__device__ __forceinline__ void store_pair(__half* C, size_t off,
                                           float v0, float v1) {
    *(__half2*)(C + off) = __floats2half2_rn(v0, v1);
}

// ---------------------------------------------------------------------------
// tf32 mma.sync GEMM with bias, dual B source, templated output type:
//   C[M,N] = A[M,K] @ B[K,N] + bias[N]
// Columns [0,N0) from (B0, ldB0, bias0); [N0,N) from (B1, ldB1, bias1);
// selection per-CTA uniform (N0 % 128 == 0). B row-major [K,*], in place.
// 128x128 CTA, BK=16 double-buffered, 256 threads (8 warps, 64x32 each).
// Smem: rows of 16 words, XOR chunk swizzle q = (k>>2) ^ ((row>>1)&3);
// ldmatrix.x4 fragment reads, conflict-free both directions.
// Requires K % 16 == 0, N % 128 == 0; M guarded.
// ---------------------------------------------------------------------------
template <typename OutT>
__global__ __launch_bounds__(256, 2) void tf32_gemm_dual(
    const float* __restrict__ A,
    const float* __restrict__ B0, int ldB0,
    const float* __restrict__ B1, int ldB1, int N0,
    const float* __restrict__ bias0, const float* __restrict__ bias1,
    OutT* __restrict__ C, int M, int N, int K)
{
    __shared__ uint32_t As[2][128 * 16];   // [m][16 words, swizzled chunks]
    __shared__ uint32_t Bs[2][128 * 16];   // [n][16 words, swizzled chunks]

    const int tid  = threadIdx.x;
    const int wid  = tid >> 5;
    const int lane = tid & 31;
    const int row0 = blockIdx.y * 128;
    const int col0 = blockIdx.x * 128;
    const int wm   = (wid >> 2) * 64;   // warp m-offset (0/64)
    const int wn   = (wid & 3) * 32;    // warp n-offset (0/32/64/96)

    // CTA-uniform B-source selection
    const bool sel = (col0 >= N0);
    const float* Bbase = sel ? (B1 + (col0 - N0)) : (B0 + col0);
    const int    ldB   = sel ? ldB1 : ldB0;
    const float* biasp = sel ? (bias1 + (col0 - N0)) : (bias0 + col0);

    float acc[4][4][4];
#pragma unroll
    for (int mt = 0; mt < 4; mt++)
#pragma unroll
        for (int nt = 0; nt < 4; nt++)
#pragma unroll
            for (int r = 0; r < 4; r++) acc[mt][nt][r] = 0.0f;

    // ---- global-load mappings ----
    const int ar = tid >> 1;           // A row 0..127
    const int ak = (tid & 1) * 8;      // 0 or 8
    const bool aok = (row0 + ar) < M;
    const float* Ap = A + (size_t)(row0 + ar) * K + ak;
    const int bn  = tid & 127;         // B local n
    const int bkh = (tid >> 7) * 8;    // 0 or 8

    // ---- smem store offsets (words), chunk-swizzled ----
    const int a_sw  = (ar >> 1) & 3;
    const int a_c0  = ak >> 2;
    const uint32_t a_off0 = ar * 16 + ((a_c0 ^ a_sw) << 2);
    const uint32_t a_off1 = ar * 16 + (((a_c0 + 1) ^ a_sw) << 2);
    const int b_sw  = (bn >> 1) & 3;
    const int b_c0  = bkh >> 2;
    const uint32_t b_off0 = bn * 16 + ((b_c0 ^ b_sw) << 2);
    const uint32_t b_off1 = bn * 16 + (((b_c0 + 1) ^ b_sw) << 2);

    // ---- ldmatrix per-lane address components ----
    const uint32_t asBase = (uint32_t)__cvta_generic_to_shared(As);
    const uint32_t bsBase = (uint32_t)__cvta_generic_to_shared(Bs);
    int a_mrow[4], a_msw[4];
#pragma unroll
    for (int mt = 0; mt < 4; mt++) {
        a_mrow[mt] = wm + mt * 16 + (lane & 7) + ((lane >> 3) & 1) * 8;
        a_msw[mt]  = (a_mrow[mt] >> 1) & 3;
    }
    const int a_cadd = lane >> 4;            // 0 or 1
    int b_nrow[2], b_nsw[2];
#pragma unroll
    for (int p = 0; p < 2; p++) {
        b_nrow[p] = wn + p * 16 + (lane & 7) + ((lane >> 4) & 1) * 8;
        b_nsw[p]  = (b_nrow[p] >> 1) & 3;
    }
    const int b_cadd = (lane >> 3) & 1;      // 0 or 1

    float4 ga0, ga1;
    float bv[8];
    auto gload = [&](int kbase) {
        if (aok) {
            ga0 = *(const float4*)(Ap + kbase);
            ga1 = *(const float4*)(Ap + kbase + 4);
        } else {
            ga0 = make_float4(0.f, 0.f, 0.f, 0.f);
            ga1 = ga0;
        }
#pragma unroll
        for (int i = 0; i < 8; i++)
            bv[i] = Bbase[(size_t)(kbase + bkh + i) * ldB + bn];
    };
    auto sstore = [&](int buf) {
        *(uint4*)&As[buf][a_off0] = make_uint4(f2tf32(ga0.x), f2tf32(ga0.y),
                                               f2tf32(ga0.z), f2tf32(ga0.w));
        *(uint4*)&As[buf][a_off1] = make_uint4(f2tf32(ga1.x), f2tf32(ga1.y),
                                               f2tf32(ga1.z), f2tf32(ga1.w));
        *(uint4*)&Bs[buf][b_off0] = make_uint4(f2tf32(bv[0]), f2tf32(bv[1]),
                                               f2tf32(bv[2]), f2tf32(bv[3]));
        *(uint4*)&Bs[buf][b_off1] = make_uint4(f2tf32(bv[4]), f2tf32(bv[5]),
                                               f2tf32(bv[6]), f2tf32(bv[7]));
    };
    auto compute = [&](int buf) {
#pragma unroll
        for (int ks = 0; ks < 2; ks++) {
            const int cb = ks * 2;
            uint32_t bfr[4][2];
#pragma unroll
            for (int p = 0; p < 2; p++) {
                uint32_t w = (uint32_t)(b_nrow[p] * 16 +
                                        (((cb + b_cadd) ^ b_nsw[p]) << 2));
                uint32_t r0, r1, r2, r3;
                ldsm_x4(r0, r1, r2, r3, bsBase + (buf * 2048u + w) * 4u);
                bfr[p * 2][0]     = r0;
                bfr[p * 2][1]     = r1;
                bfr[p * 2 + 1][0] = r2;
                bfr[p * 2 + 1][1] = r3;
            }
#pragma unroll
            for (int mt = 0; mt < 4; mt++) {
                uint32_t w = (uint32_t)(a_mrow[mt] * 16 +
                                        (((cb + a_cadd) ^ a_msw[mt]) << 2));
                uint32_t afr[4];
                ldsm_x4(afr[0], afr[1], afr[2], afr[3],
                        asBase + (buf * 2048u + w) * 4u);
#pragma unroll
                for (int nt = 0; nt < 4; nt++)
                    mma_tf32(acc[mt][nt], afr, bfr[nt]);
            }
        }
    };

    const int nstage = K >> 4;
    gload(0);
    sstore(0);
    __syncthreads();
    for (int s = 0; s < nstage; s++) {
        if (s + 1 < nstage) gload((s + 1) << 4);
        compute(s & 1);
        if (s + 1 < nstage) {
            sstore((s + 1) & 1);
            __syncthreads();
        }
    }

    // Epilogue: direct pair stores (float2 or half2)
    const int g = lane >> 2;
    const int c = lane & 3;
#pragma unroll
    for (int nt = 0; nt < 4; nt++) {
        const int cl  = wn + nt * 8 + c * 2;
        const float b0v = __ldg(biasp + cl);
        const float b1v = __ldg(biasp + cl + 1);
#pragma unroll
        for (int mt = 0; mt < 4; mt++) {
            const int r0 = row0 + wm + mt * 16 + g;
            if (r0 < M)
                store_pair(C, (size_t)r0 * N + col0 + cl,
                           acc[mt][nt][0] + b0v, acc[mt][nt][1] + b1v);
            if (r0 + 8 < M)
                store_pair(C, (size_t)(r0 + 8) * N + col0 + cl,
                           acc[mt][nt][2] + b0v, acc[mt][nt][3] + b1v);
        }
    }
}

// ---------------------------------------------------------------------------
// Sampling + in-warp softmax: one warp per (b, q, h); lane = head-dim channel.
// V is fp16 [B*LV, 256]; SOAW row layout: [so (256) | aw logits (128)].
// ---------------------------------------------------------------------------
__global__ __launch_bounds__(256) void sample_kernel(
    const float*  __restrict__ ref,    // [B, LQ, 4, 2]
    const __half* __restrict__ v,      // [B, LV, H, HD] fp16
    const float*  __restrict__ soaw,   // [B*LQ, 384]
    float* __restrict__ acc_out)       // [B*LQ, 256]
{
    const int w    = blockIdx.x * 8 + (threadIdx.x >> 5);
    const int lane = threadIdx.x & 31;
    const int h    = w & 7;
    const int bq   = w >> 3;
    const int b    = bq >> 10;

    const float* row   = soaw + (size_t)bq * 384;
    const float* so_p  = row + h * 32;
    const float* aw_p  = row + 256 + h * 16;
    const float* ref_p = ref + (size_t)bq * 8;
    const __half* vb   = v + (size_t)b * cfg::LV * cfg::D + h * 32 + lane;

    // In-warp softmax over 16 logits (xor-8/4/2/1 stays within 16-lane halves)
    float logit = (lane < 16) ? aw_p[lane] : -1e30f;
    float mx = logit;
#pragma unroll
    for (int off = 8; off >= 1; off >>= 1)
        mx = fmaxf(mx, __shfl_xor_sync(0xffffffffu, mx, off));
    float e = __expf(logit - mx);
    float ssum = e;
#pragma unroll
    for (int off = 8; off >= 1; off >>= 1)
        ssum += __shfl_xor_sync(0xffffffffu, ssum, off);
    const float wnorm = e / ssum;     // valid on lanes 0..15

    const int LHW[4]    = {100, 50, 25, 13};
    const int LSTART[4] = {0, 10000, 12500, 13125};

    float acc = 0.0f;
#pragma unroll
    for (int l = 0; l < 4; l++) {
        const int   Wl = LHW[l];
        const int   Hl = LHW[l];
        const float bx = ref_p[l * 2 + 0] * (float)Wl - 0.5f;
        const float by = ref_p[l * 2 + 1] * (float)Hl - 0.5f;
        const __half* base = vb + (size_t)LSTART[l] * cfg::D;

#pragma unroll
        for (int p = 0; p < 4; p++) {
            const float x  = bx + so_p[(l * 4 + p) * 2 + 0];
            const float y  = by + so_p[(l * 4 + p) * 2 + 1];
            const float wt = __shfl_sync(0xffffffffu, wnorm, l * 4 + p);

            const float x0f = floorf(x), y0f = floorf(y);
            const int   ix0 = (int)x0f,  iy0 = (int)y0f;
            const float fx = x - x0f,    fy = y - y0f;

            const bool vx0 = (ix0 >= 0)     && (ix0 < Wl);
            const bool vx1 = (ix0 + 1 >= 0) && (ix0 + 1 < Wl);
            const bool vy0 = (iy0 >= 0)     && (iy0 < Hl);
            const bool vy1 = (iy0 + 1 >= 0) && (iy0 + 1 < Hl);

            float v00 = 0.f, v01 = 0.f, v10 = 0.f, v11 = 0.f;
            if (vy0) {
                const __half* r0 = base + (size_t)(iy0 * Wl) * cfg::D;
                if (vx0) v00 = __half2float(__ldg(r0 + (size_t)ix0 * cfg::D));
                if (vx1) v01 = __half2float(__ldg(r0 + (size_t)(ix0 + 1) * cfg::D));
            }
            if (vy1) {
                const __half* r1 = base + (size_t)((iy0 + 1) * Wl) * cfg::D;
                if (vx0) v10 = __half2float(__ldg(r1 + (size_t)ix0 * cfg::D));
                if (vx1) v11 = __half2float(__ldg(r1 + (size_t)(ix0 + 1) * cfg::D));
            }

            const float top = v00 * (1.f - fx) + v01 * fx;
            const float bot = v10 * (1.f - fx) + v11 * fx;
            acc = fmaf(wt, top * (1.f - fy) + bot * fy, acc);
        }
    }
    acc_out[(size_t)bq * 256 + h * 32 + lane] = acc;
}

// ---------------------------------------------------------------------------
// Launch
// ---------------------------------------------------------------------------
extern "C" void kernel_launch(void* const* d_in, const int* in_sizes, int n_in,
                              void* d_out, int out_size)
{
    const float* query = (const float*)d_in[0];   // [8,1024,256]
    const float* refp  = (const float*)d_in[1];   // [8,1024,4,2]
    const float* value = (const float*)d_in[2];   // [8,13294,256]
    // d_in[3] = value_spatial_shapes (compile-time constant)
    const float* so_w  = (const float*)d_in[4];   // [256,256]  [K,N]
    const float* so_b  = (const float*)d_in[5];
    const float* aw_w  = (const float*)d_in[6];   // [256,128]  [K,N]
    const float* aw_b  = (const float*)d_in[7];
    const float* vp_w  = (const float*)d_in[8];   // [256,256]  [K,N]
    const float* vp_b  = (const float*)d_in[9];
    const float* op_w  = (const float*)d_in[10];  // [256,256]  [K,N]
    const float* op_b  = (const float*)d_in[11];
    float* out = (float*)d_out;                   // [8,1024,256]

    float* scratch = nullptr;
    cudaGetSymbolAddress((void**)&scratch, g_scratch);
    __half* sV   = (__half*)(scratch + cfg::OFF_V);
    float* sSOAW = scratch + cfg::OFF_SOAW;
    float* sACC  = scratch + cfg::OFF_ACC;

    const int MQ = cfg::B * cfg::LQ;      // 8192
    const int MV = cfg::B * cfg::LV;      // 106352

    // 1) v = value @ vp_w + vp_b  -> fp16
    tf32_gemm_dual<__half><<<dim3(2, (MV + 127) / 128), 256>>>(
        value, vp_w, 256, vp_w, 256, 256, vp_b, vp_b, sV, MV, 256, 256);
    // 2) soaw = query @ [so_w | aw_w] + [so_b | aw_b]  (split at col 256)
    tf32_gemm_dual<float><<<dim3(3, MQ / 128), 256>>>(
        query, so_w, 256, aw_w, 128, 256, so_b, aw_b, sSOAW, MQ, 384, 256);
    // 3) sampling (softmax folded in, fp16 V gathers)
    {
        int warps = cfg::B * cfg::LQ * cfg::H;   // 65536
        sample_kernel<<<warps / 8, 256>>>(refp, sV, sSOAW, sACC);
    }
    // 4) out = ACC @ op_w + op_b
    tf32_gemm_dual<float><<<dim3(2, MQ / 128), 256>>>(
        sACC, op_w, 256, op_w, 256, 256, op_b, op_b, out, MQ, 256, 256);
}

// round 12
// speedup vs baseline: 1.0522x; 1.0522x over previous
#include <cuda_runtime.h>
#include <math.h>
#include <stdint.h>

// ---------------------------------------------------------------------------
// MSDeformableAttention — GB300 (plain sm_103 target: tcgen05 unavailable,
// legacy mma.sync tf32 tensor path, ldmatrix fragment loads,
// cp.async 4-stage smem pipeline)
//
//   1) tf32_gemm: v    = value @ vp_w + vp_b            -> V [B*LV, 256]
//   2) tf32_gemm: soaw = query @ [so_w | aw_w] + bias   -> SOAW [B*LQ, 384]
//   3) sample: in-warp softmax + bilinear gather        -> ACC [B*LQ, 256]
//   4) tf32_gemm: out = ACC @ op_w + op_b
//
// B=8, LQ=1024, LV=13294, D=256, H=8, HD=32, L=4, P=4
// levels (h=w,start): (100,0) (50,10000) (25,12500) (13,13125)
// ---------------------------------------------------------------------------

namespace cfg {
constexpr int B  = 8;
constexpr int LQ = 1024;
constexpr int LV = 13294;
constexpr int D  = 256;
constexpr int H  = 8;

constexpr size_t SZ_V    = (size_t)B * LV * D;      // 27,226,112
constexpr size_t SZ_SOAW = (size_t)B * LQ * 384;
constexpr size_t SZ_ACC  = (size_t)B * LQ * D;

constexpr size_t OFF_V    = 0;
constexpr size_t OFF_SOAW = OFF_V    + SZ_V;
constexpr size_t OFF_ACC  = OFF_SOAW + SZ_SOAW;
constexpr size_t SZ_TOT   = OFF_ACC  + SZ_ACC;      // ~32.5M floats (~130 MB)
}  // namespace cfg

__device__ float g_scratch[cfg::SZ_TOT];

// ---------------------------------------------------------------------------
__device__ __forceinline__ uint32_t f2tf32(float x) {
    uint32_t u;
    asm("cvt.rna.tf32.f32 %0, %1;" : "=r"(u) : "f"(x));
    return u;
}
__device__ __forceinline__ uint32_t frag_tf32(uint32_t bits) {
    return f2tf32(__uint_as_float(bits));
}

__device__ __forceinline__ void mma_tf32(float d[4], const uint32_t a[4],
                                         const uint32_t b[2]) {
    asm volatile(
        "mma.sync.aligned.m16n8k8.row.col.f32.tf32.tf32.f32 "
        "{%0,%1,%2,%3}, {%4,%5,%6,%7}, {%8,%9}, {%0,%1,%2,%3};"
        : "+f"(d[0]), "+f"(d[1]), "+f"(d[2]), "+f"(d[3])
        : "r"(a[0]), "r"(a[1]), "r"(a[2]), "r"(a[3]), "r"(b[0]), "r"(b[1]));
}

__device__ __forceinline__ void ldsm_x4(uint32_t& r0, uint32_t& r1,
                                        uint32_t& r2, uint32_t& r3,
                                        uint32_t saddr) {
    asm volatile(
        "ldmatrix.sync.aligned.m8n8.x4.shared.b16 {%0,%1,%2,%3}, [%4];"
        : "=r"(r0), "=r"(r1), "=r"(r2), "=r"(r3) : "r"(saddr));
}

__device__ __forceinline__ void cpa16(uint32_t dst, const void* src,
                                      int src_bytes) {
    asm volatile("cp.async.cg.shared.global [%0], [%1], 16, %2;"
                 :: "r"(dst), "l"(src), "r"(src_bytes));
}
__device__ __forceinline__ void cpa4(uint32_t dst, const void* src) {
    asm volatile("cp.async.ca.shared.global [%0], [%1], 4;"
                 :: "r"(dst), "l"(src));
}
__device__ __forceinline__ void cpa_commit() {
    asm volatile("cp.async.commit_group;");
}
__device__ __forceinline__ void cpa_wait2() {
    asm volatile("cp.async.wait_group 2;");
}

// ---------------------------------------------------------------------------
// tf32 mma.sync GEMM with bias, dual B source:
//   C[M,N] = A[M,K] @ B[K,N] + bias[N]
// Columns [0,N0) from (B0, ldB0, bias0); [N0,N) from (B1, ldB1, bias1);
// selection per-CTA uniform (N0 % 128 == 0). B row-major [K,*], in place.
// 128x128 CTA, BK=16, 4-stage cp.async pipeline, 256 threads
// (8 warps, 64x32 warp tile). Smem rows of 16 words, XOR chunk swizzle
// q = (k>>2) ^ ((row>>1)&3); ldmatrix.x4 reads; raw fp32 bits in smem,
// tf32 rounding applied to fragments (cvt.rna) before mma.
// Requires K % 16 == 0, N % 128 == 0; M guarded.
// ---------------------------------------------------------------------------
__global__ __launch_bounds__(256, 2) void tf32_gemm_dual(
    const float* __restrict__ A,
    const float* __restrict__ B0, int ldB0,
    const float* __restrict__ B1, int ldB1, int N0,
    const float* __restrict__ bias0, const float* __restrict__ bias1,
    float* __restrict__ C, int M, int N, int K)
{
    constexpr int NSTAGE = 4;
    __shared__ uint32_t As[NSTAGE][128 * 16];
    __shared__ uint32_t Bs[NSTAGE][128 * 16];

    const int tid  = threadIdx.x;
    const int wid  = tid >> 5;
    const int lane = tid & 31;
    const int row0 = blockIdx.y * 128;
    const int col0 = blockIdx.x * 128;
    const int wm   = (wid >> 2) * 64;
    const int wn   = (wid & 3) * 32;

    // CTA-uniform B-source selection
    const bool sel = (col0 >= N0);
    const float* Bbase = sel ? (B1 + (col0 - N0)) : (B0 + col0);
    const int    ldB   = sel ? ldB1 : ldB0;
    const float* biasp = sel ? (bias1 + (col0 - N0)) : (bias0 + col0);

    float acc[4][4][4];
#pragma unroll
    for (int mt = 0; mt < 4; mt++)
#pragma unroll
        for (int nt = 0; nt < 4; nt++)
#pragma unroll
            for (int r = 0; r < 4; r++) acc[mt][nt][r] = 0.0f;

    // ---- global-load mappings ----
    const int ar = tid >> 1;           // A row 0..127
    const int ak = (tid & 1) * 8;      // 0 or 8
    const bool aok = (row0 + ar) < M;
    const int a_srcb = aok ? 16 : 0;   // cp.async src-size (zfill OOB rows)
    const float* Ap = A + (size_t)(aok ? (row0 + ar) : 0) * K + ak;
    const int bn  = tid & 127;         // B local n
    const int bkh = (tid >> 7) * 8;    // 0 or 8

    // ---- smem store offsets (words), chunk-swizzled ----
    const int a_sw  = (ar >> 1) & 3;
    const int a_c0  = ak >> 2;
    const uint32_t a_off0 = ar * 16 + ((a_c0 ^ a_sw) << 2);
    const uint32_t a_off1 = ar * 16 + (((a_c0 + 1) ^ a_sw) << 2);
    const int b_sw  = (bn >> 1) & 3;
    const int b_c0  = bkh >> 2;
    const uint32_t b_off0 = bn * 16 + ((b_c0 ^ b_sw) << 2);
    const uint32_t b_off1 = bn * 16 + (((b_c0 + 1) ^ b_sw) << 2);

    const uint32_t asBase = (uint32_t)__cvta_generic_to_shared(As);
    const uint32_t bsBase = (uint32_t)__cvta_generic_to_shared(Bs);

    // ---- ldmatrix per-lane address components ----
    int a_mrow[4], a_msw[4];
#pragma unroll
    for (int mt = 0; mt < 4; mt++) {
        a_mrow[mt] = wm + mt * 16 + (lane & 7) + ((lane >> 3) & 1) * 8;
        a_msw[mt]  = (a_mrow[mt] >> 1) & 3;
    }
    const int a_cadd = lane >> 4;
    int b_nrow[2], b_nsw[2];
#pragma unroll
    for (int p = 0; p < 2; p++) {
        b_nrow[p] = wn + p * 16 + (lane & 7) + ((lane >> 4) & 1) * 8;
        b_nsw[p]  = (b_nrow[p] >> 1) & 3;
    }
    const int b_cadd = (lane >> 3) & 1;

    auto issue_copy = [&](int slot, int kbase) {
        const uint32_t aslot = asBase + (uint32_t)slot * 8192u;  // 2048 words
        const uint32_t bslot = bsBase + (uint32_t)slot * 8192u;
        cpa16(aslot + a_off0 * 4u, Ap + kbase, a_srcb);
        cpa16(aslot + a_off1 * 4u, Ap + kbase + 4, a_srcb);
        const float* bp = Bbase + (size_t)(kbase + bkh) * ldB + bn;
#pragma unroll
        for (int i = 0; i < 4; i++)
            cpa4(bslot + (b_off0 + i) * 4u, bp + (size_t)i * ldB);
#pragma unroll
        for (int i = 0; i < 4; i++)
            cpa4(bslot + (b_off1 + i) * 4u, bp + (size_t)(i + 4) * ldB);
    };

    auto compute = [&](int buf) {
        const uint32_t aslot = asBase + (uint32_t)buf * 8192u;
        const uint32_t bslot = bsBase + (uint32_t)buf * 8192u;
#pragma unroll
        for (int ks = 0; ks < 2; ks++) {
            const int cb = ks * 2;
            uint32_t bfr[4][2];
#pragma unroll
            for (int p = 0; p < 2; p++) {
                uint32_t w = (uint32_t)(b_nrow[p] * 16 +
                                        (((cb + b_cadd) ^ b_nsw[p]) << 2));
                uint32_t r0, r1, r2, r3;
                ldsm_x4(r0, r1, r2, r3, bslot + w * 4u);
                bfr[p * 2][0]     = frag_tf32(r0);
                bfr[p * 2][1]     = frag_tf32(r1);
                bfr[p * 2 + 1][0] = frag_tf32(r2);
                bfr[p * 2 + 1][1] = frag_tf32(r3);
            }
#pragma unroll
            for (int mt = 0; mt < 4; mt++) {
                uint32_t w = (uint32_t)(a_mrow[mt] * 16 +
                                        (((cb + a_cadd) ^ a_msw[mt]) << 2));
                uint32_t afr[4];
                ldsm_x4(afr[0], afr[1], afr[2], afr[3], aslot + w * 4u);
                afr[0] = frag_tf32(afr[0]);
                afr[1] = frag_tf32(afr[1]);
                afr[2] = frag_tf32(afr[2]);
                afr[3] = frag_tf32(afr[3]);
#pragma unroll
                for (int nt = 0; nt < 4; nt++)
                    mma_tf32(acc[mt][nt], afr, bfr[nt]);
            }
        }
    };

    const int nstage = K >> 4;
    // Prologue: 3 stages in flight
#pragma unroll
    for (int s = 0; s < 3; s++) {
        if (s < nstage) issue_copy(s, s << 4);
        cpa_commit();
    }
    cpa_wait2();
    __syncthreads();

    for (int s = 0; s < nstage; s++) {
        if (s + 3 < nstage) issue_copy((s + 3) & 3, (s + 3) << 4);
        cpa_commit();              // empty group at tail keeps FIFO aligned
        compute(s & 3);
        cpa_wait2();
        __syncthreads();
    }

    // Epilogue: direct float2 stores
    const int g = lane >> 2;
    const int c = lane & 3;
#pragma unroll
    for (int nt = 0; nt < 4; nt++) {
        const int cl  = wn + nt * 8 + c * 2;
        const float b0v = __ldg(biasp + cl);
        const float b1v = __ldg(biasp + cl + 1);
#pragma unroll
        for (int mt = 0; mt < 4; mt++) {
            const int r0 = row0 + wm + mt * 16 + g;
            if (r0 < M) {
                float2 o = make_float2(acc[mt][nt][0] + b0v, acc[mt][nt][1] + b1v);
                *(float2*)(C + (size_t)r0 * N + col0 + cl) = o;
            }
            if (r0 + 8 < M) {
                float2 o = make_float2(acc[mt][nt][2] + b0v, acc[mt][nt][3] + b1v);
                *(float2*)(C + (size_t)(r0 + 8) * N + col0 + cl) = o;
            }
        }
    }
}

// ---------------------------------------------------------------------------
// Sampling + in-warp softmax: one warp per (b, q, h); lane = head-dim channel.
// SOAW row layout: [so (256) | aw logits (128)]  stride 384.
// ---------------------------------------------------------------------------
__global__ __launch_bounds__(256) void sample_kernel(
    const float* __restrict__ ref,    // [B, LQ, 4, 2]
    const float* __restrict__ v,      // [B, LV, H, HD]
    const float* __restrict__ soaw,   // [B*LQ, 384]
    float* __restrict__ acc_out)      // [B*LQ, 256]
{
    const int w    = blockIdx.x * 8 + (threadIdx.x >> 5);
    const int lane = threadIdx.x & 31;
    const int h    = w & 7;
    const int bq   = w >> 3;
    const int b    = bq >> 10;

    const float* row   = soaw + (size_t)bq * 384;
    const float* so_p  = row + h * 32;
    const float* aw_p  = row + 256 + h * 16;
    const float* ref_p = ref + (size_t)bq * 8;
    const float* vb    = v + (size_t)b * cfg::LV * cfg::D + h * 32 + lane;

    // In-warp softmax over 16 logits (xor-8/4/2/1 stays within 16-lane halves)
    float logit = (lane < 16) ? aw_p[lane] : -1e30f;
    float mx = logit;
#pragma unroll
    for (int off = 8; off >= 1; off >>= 1)
        mx = fmaxf(mx, __shfl_xor_sync(0xffffffffu, mx, off));
    float e = __expf(logit - mx);
    float ssum = e;
#pragma unroll
    for (int off = 8; off >= 1; off >>= 1)
        ssum += __shfl_xor_sync(0xffffffffu, ssum, off);
    const float wnorm = e / ssum;     // valid on lanes 0..15

    const int LHW[4]    = {100, 50, 25, 13};
    const int LSTART[4] = {0, 10000, 12500, 13125};

    float acc = 0.0f;
#pragma unroll
    for (int l = 0; l < 4; l++) {
        const int   Wl = LHW[l];
        const int   Hl = LHW[l];
        const float bx = ref_p[l * 2 + 0] * (float)Wl - 0.5f;
        const float by = ref_p[l * 2 + 1] * (float)Hl - 0.5f;
        const float* base = vb + (size_t)LSTART[l] * cfg::D;

#pragma unroll
        for (int p = 0; p < 4; p++) {
            const float x  = bx + so_p[(l * 4 + p) * 2 + 0];
            const float y  = by + so_p[(l * 4 + p) * 2 + 1];
            const float wt = __shfl_sync(0xffffffffu, wnorm, l * 4 + p);

            const float x0f = floorf(x), y0f = floorf(y);
            const int   ix0 = (int)x0f,  iy0 = (int)y0f;
            const float fx = x - x0f,    fy = y - y0f;

            const bool vx0 = (ix0 >= 0)     && (ix0 < Wl);
            const bool vx1 = (ix0 + 1 >= 0) && (ix0 + 1 < Wl);
            const bool vy0 = (iy0 >= 0)     && (iy0 < Hl);
            const bool vy1 = (iy0 + 1 >= 0) && (iy0 + 1 < Hl);

            float v00 = 0.f, v01 = 0.f, v10 = 0.f, v11 = 0.f;
            if (vy0) {
                const float* r0 = base + (size_t)(iy0 * Wl) * cfg::D;
                if (vx0) v00 = __ldg(r0 + (size_t)ix0 * cfg::D);
                if (vx1) v01 = __ldg(r0 + (size_t)(ix0 + 1) * cfg::D);
            }
            if (vy1) {
                const float* r1 = base + (size_t)((iy0 + 1) * Wl) * cfg::D;
                if (vx0) v10 = __ldg(r1 + (size_t)ix0 * cfg::D);
                if (vx1) v11 = __ldg(r1 + (size_t)(ix0 + 1) * cfg::D);
            }

            const float top = v00 * (1.f - fx) + v01 * fx;
            const float bot = v10 * (1.f - fx) + v11 * fx;
            acc = fmaf(wt, top * (1.f - fy) + bot * fy, acc);
        }
    }
    acc_out[(size_t)bq * 256 + h * 32 + lane] = acc;
}

// ---------------------------------------------------------------------------
// Launch
// ---------------------------------------------------------------------------
extern "C" void kernel_launch(void* const* d_in, const int* in_sizes, int n_in,
                              void* d_out, int out_size)
{
    const float* query = (const float*)d_in[0];   // [8,1024,256]
    const float* refp  = (const float*)d_in[1];   // [8,1024,4,2]
    const float* value = (const float*)d_in[2];   // [8,13294,256]
    // d_in[3] = value_spatial_shapes (compile-time constant)
    const float* so_w  = (const float*)d_in[4];   // [256,256]  [K,N]
    const float* so_b  = (const float*)d_in[5];
    const float* aw_w  = (const float*)d_in[6];   // [256,128]  [K,N]
    const float* aw_b  = (const float*)d_in[7];
    const float* vp_w  = (const float*)d_in[8];   // [256,256]  [K,N]
    const float* vp_b  = (const float*)d_in[9];
    const float* op_w  = (const float*)d_in[10];  // [256,256]  [K,N]
    const float* op_b  = (const float*)d_in[11];
    float* out = (float*)d_out;                   // [8,1024,256]

    float* scratch = nullptr;
    cudaGetSymbolAddress((void**)&scratch, g_scratch);
    float* sV    = scratch + cfg::OFF_V;
    float* sSOAW = scratch + cfg::OFF_SOAW;
    float* sACC  = scratch + cfg::OFF_ACC;

    const int MQ = cfg::B * cfg::LQ;      // 8192
    const int MV = cfg::B * cfg::LV;      // 106352

    // 1) v = value @ vp_w + vp_b
    tf32_gemm_dual<<<dim3(2, (MV + 127) / 128), 256>>>(
        value, vp_w, 256, vp_w, 256, 256, vp_b, vp_b, sV, MV, 256, 256);
    // 2) soaw = query @ [so_w | aw_w] + [so_b | aw_b]  (split at col 256)
    tf32_gemm_dual<<<dim3(3, MQ / 128), 256>>>(
        query, so_w, 256, aw_w, 128, 256, so_b, aw_b, sSOAW, MQ, 384, 256);
    // 3) sampling (softmax folded in)
    {
        int warps = cfg::B * cfg::LQ * cfg::H;   // 65536
        sample_kernel<<<warps / 8, 256>>>(refp, sV, sSOAW, sACC);
    }
    // 4) out = ACC @ op_w + op_b
    tf32_gemm_dual<<<dim3(2, MQ / 128), 256>>>(
        sACC, op_w, 256, op_w, 256, 256, op_b, op_b, out, MQ, 256, 256);
}

// round 13
// speedup vs baseline: 1.1823x; 1.1236x over previous
#include <cuda_runtime.h>
#include <math.h>
#include <stdint.h>

// ---------------------------------------------------------------------------
// MSDeformableAttention — GB300 (plain sm_103 target: tcgen05 unavailable,
// legacy mma.sync tf32 tensor path, ldmatrix fragment loads,
// cp.async 4-stage smem pipeline; sample kernel: 2 points/warp, float2 lanes)
//
//   1) tf32_gemm: v    = value @ vp_w + vp_b            -> V [B*LV, 256]
//   2) tf32_gemm: soaw = query @ [so_w | aw_w] + bias   -> SOAW [B*LQ, 384]
//   3) sample: in-warp softmax + bilinear gather        -> ACC [B*LQ, 256]
//   4) tf32_gemm: out = ACC @ op_w + op_b
//
// B=8, LQ=1024, LV=13294, D=256, H=8, HD=32, L=4, P=4
// levels (h=w,start): (100,0) (50,10000) (25,12500) (13,13125)
// ---------------------------------------------------------------------------

namespace cfg {
constexpr int B  = 8;
constexpr int LQ = 1024;
constexpr int LV = 13294;
constexpr int D  = 256;
constexpr int H  = 8;

constexpr size_t SZ_V    = (size_t)B * LV * D;      // 27,226,112
constexpr size_t SZ_SOAW = (size_t)B * LQ * 384;
constexpr size_t SZ_ACC  = (size_t)B * LQ * D;

constexpr size_t OFF_V    = 0;
constexpr size_t OFF_SOAW = OFF_V    + SZ_V;
constexpr size_t OFF_ACC  = OFF_SOAW + SZ_SOAW;
constexpr size_t SZ_TOT   = OFF_ACC  + SZ_ACC;      // ~32.5M floats (~130 MB)
}  // namespace cfg

__device__ float g_scratch[cfg::SZ_TOT];

// ---------------------------------------------------------------------------
__device__ __forceinline__ uint32_t f2tf32(float x) {
    uint32_t u;
    asm("cvt.rna.tf32.f32 %0, %1;" : "=r"(u) : "f"(x));
    return u;
}
__device__ __forceinline__ uint32_t frag_tf32(uint32_t bits) {
    return f2tf32(__uint_as_float(bits));
}

__device__ __forceinline__ void mma_tf32(float d[4], const uint32_t a[4],
                                         const uint32_t b[2]) {
    asm volatile(
        "mma.sync.aligned.m16n8k8.row.col.f32.tf32.tf32.f32 "
        "{%0,%1,%2,%3}, {%4,%5,%6,%7}, {%8,%9}, {%0,%1,%2,%3};"
        : "+f"(d[0]), "+f"(d[1]), "+f"(d[2]), "+f"(d[3])
        : "r"(a[0]), "r"(a[1]), "r"(a[2]), "r"(a[3]), "r"(b[0]), "r"(b[1]));
}

__device__ __forceinline__ void ldsm_x4(uint32_t& r0, uint32_t& r1,
                                        uint32_t& r2, uint32_t& r3,
                                        uint32_t saddr) {
    asm volatile(
        "ldmatrix.sync.aligned.m8n8.x4.shared.b16 {%0,%1,%2,%3}, [%4];"
        : "=r"(r0), "=r"(r1), "=r"(r2), "=r"(r3) : "r"(saddr));
}

__device__ __forceinline__ void cpa16(uint32_t dst, const void* src,
                                      int src_bytes) {
    asm volatile("cp.async.cg.shared.global [%0], [%1], 16, %2;"
                 :: "r"(dst), "l"(src), "r"(src_bytes));
}
__device__ __forceinline__ void cpa4(uint32_t dst, const void* src) {
    asm volatile("cp.async.ca.shared.global [%0], [%1], 4;"
                 :: "r"(dst), "l"(src));
}
__device__ __forceinline__ void cpa_commit() {
    asm volatile("cp.async.commit_group;");
}
__device__ __forceinline__ void cpa_wait2() {
    asm volatile("cp.async.wait_group 2;");
}

// ---------------------------------------------------------------------------
// tf32 mma.sync GEMM with bias, dual B source (unchanged from R12):
//   C[M,N] = A[M,K] @ B[K,N] + bias[N]
// ---------------------------------------------------------------------------
__global__ __launch_bounds__(256, 2) void tf32_gemm_dual(
    const float* __restrict__ A,
    const float* __restrict__ B0, int ldB0,
    const float* __restrict__ B1, int ldB1, int N0,
    const float* __restrict__ bias0, const float* __restrict__ bias1,
    float* __restrict__ C, int M, int N, int K)
{
    constexpr int NSTAGE = 4;
    __shared__ uint32_t As[NSTAGE][128 * 16];
    __shared__ uint32_t Bs[NSTAGE][128 * 16];

    const int tid  = threadIdx.x;
    const int wid  = tid >> 5;
    const int lane = tid & 31;
    const int row0 = blockIdx.y * 128;
    const int col0 = blockIdx.x * 128;
    const int wm   = (wid >> 2) * 64;
    const int wn   = (wid & 3) * 32;

    const bool sel = (col0 >= N0);
    const float* Bbase = sel ? (B1 + (col0 - N0)) : (B0 + col0);
    const int    ldB   = sel ? ldB1 : ldB0;
    const float* biasp = sel ? (bias1 + (col0 - N0)) : (bias0 + col0);

    float acc[4][4][4];
#pragma unroll
    for (int mt = 0; mt < 4; mt++)
#pragma unroll
        for (int nt = 0; nt < 4; nt++)
#pragma unroll
            for (int r = 0; r < 4; r++) acc[mt][nt][r] = 0.0f;

    const int ar = tid >> 1;
    const int ak = (tid & 1) * 8;
    const bool aok = (row0 + ar) < M;
    const int a_srcb = aok ? 16 : 0;
    const float* Ap = A + (size_t)(aok ? (row0 + ar) : 0) * K + ak;
    const int bn  = tid & 127;
    const int bkh = (tid >> 7) * 8;

    const int a_sw  = (ar >> 1) & 3;
    const int a_c0  = ak >> 2;
    const uint32_t a_off0 = ar * 16 + ((a_c0 ^ a_sw) << 2);
    const uint32_t a_off1 = ar * 16 + (((a_c0 + 1) ^ a_sw) << 2);
    const int b_sw  = (bn >> 1) & 3;
    const int b_c0  = bkh >> 2;
    const uint32_t b_off0 = bn * 16 + ((b_c0 ^ b_sw) << 2);
    const uint32_t b_off1 = bn * 16 + (((b_c0 + 1) ^ b_sw) << 2);

    const uint32_t asBase = (uint32_t)__cvta_generic_to_shared(As);
    const uint32_t bsBase = (uint32_t)__cvta_generic_to_shared(Bs);

    int a_mrow[4], a_msw[4];
#pragma unroll
    for (int mt = 0; mt < 4; mt++) {
        a_mrow[mt] = wm + mt * 16 + (lane & 7) + ((lane >> 3) & 1) * 8;
        a_msw[mt]  = (a_mrow[mt] >> 1) & 3;
    }
    const int a_cadd = lane >> 4;
    int b_nrow[2], b_nsw[2];
#pragma unroll
    for (int p = 0; p < 2; p++) {
        b_nrow[p] = wn + p * 16 + (lane & 7) + ((lane >> 4) & 1) * 8;
        b_nsw[p]  = (b_nrow[p] >> 1) & 3;
    }
    const int b_cadd = (lane >> 3) & 1;

    auto issue_copy = [&](int slot, int kbase) {
        const uint32_t aslot = asBase + (uint32_t)slot * 8192u;
        const uint32_t bslot = bsBase + (uint32_t)slot * 8192u;
        cpa16(aslot + a_off0 * 4u, Ap + kbase, a_srcb);
        cpa16(aslot + a_off1 * 4u, Ap + kbase + 4, a_srcb);
        const float* bp = Bbase + (size_t)(kbase + bkh) * ldB + bn;
#pragma unroll
        for (int i = 0; i < 4; i++)
            cpa4(bslot + (b_off0 + i) * 4u, bp + (size_t)i * ldB);
#pragma unroll
        for (int i = 0; i < 4; i++)
            cpa4(bslot + (b_off1 + i) * 4u, bp + (size_t)(i + 4) * ldB);
    };

    auto compute = [&](int buf) {
        const uint32_t aslot = asBase + (uint32_t)buf * 8192u;
        const uint32_t bslot = bsBase + (uint32_t)buf * 8192u;
#pragma unroll
        for (int ks = 0; ks < 2; ks++) {
            const int cb = ks * 2;
            uint32_t bfr[4][2];
#pragma unroll
            for (int p = 0; p < 2; p++) {
                uint32_t w = (uint32_t)(b_nrow[p] * 16 +
                                        (((cb + b_cadd) ^ b_nsw[p]) << 2));
                uint32_t r0, r1, r2, r3;
                ldsm_x4(r0, r1, r2, r3, bslot + w * 4u);
                bfr[p * 2][0]     = frag_tf32(r0);
                bfr[p * 2][1]     = frag_tf32(r1);
                bfr[p * 2 + 1][0] = frag_tf32(r2);
                bfr[p * 2 + 1][1] = frag_tf32(r3);
            }
#pragma unroll
            for (int mt = 0; mt < 4; mt++) {
                uint32_t w = (uint32_t)(a_mrow[mt] * 16 +
                                        (((cb + a_cadd) ^ a_msw[mt]) << 2));
                uint32_t afr[4];
                ldsm_x4(afr[0], afr[1], afr[2], afr[3], aslot + w * 4u);
                afr[0] = frag_tf32(afr[0]);
                afr[1] = frag_tf32(afr[1]);
                afr[2] = frag_tf32(afr[2]);
                afr[3] = frag_tf32(afr[3]);
#pragma unroll
                for (int nt = 0; nt < 4; nt++)
                    mma_tf32(acc[mt][nt], afr, bfr[nt]);
            }
        }
    };

    const int nstage = K >> 4;
#pragma unroll
    for (int s = 0; s < 3; s++) {
        if (s < nstage) issue_copy(s, s << 4);
        cpa_commit();
    }
    cpa_wait2();
    __syncthreads();

    for (int s = 0; s < nstage; s++) {
        if (s + 3 < nstage) issue_copy((s + 3) & 3, (s + 3) << 4);
        cpa_commit();
        compute(s & 3);
        cpa_wait2();
        __syncthreads();
    }

    const int g = lane >> 2;
    const int c = lane & 3;
#pragma unroll
    for (int nt = 0; nt < 4; nt++) {
        const int cl  = wn + nt * 8 + c * 2;
        const float b0v = __ldg(biasp + cl);
        const float b1v = __ldg(biasp + cl + 1);
#pragma unroll
        for (int mt = 0; mt < 4; mt++) {
            const int r0 = row0 + wm + mt * 16 + g;
            if (r0 < M) {
                float2 o = make_float2(acc[mt][nt][0] + b0v, acc[mt][nt][1] + b1v);
                *(float2*)(C + (size_t)r0 * N + col0 + cl) = o;
            }
            if (r0 + 8 < M) {
                float2 o = make_float2(acc[mt][nt][2] + b0v, acc[mt][nt][3] + b1v);
                *(float2*)(C + (size_t)(r0 + 8) * N + col0 + cl) = o;
            }
        }
    }
}

// ---------------------------------------------------------------------------
// Sampling + in-warp softmax: one warp per (b, q, h).
// Warp split into two 16-lane halves, each half processes one point of a
// pair; each lane carries 2 channels (float2). 8 iterations cover all 16
// samples; point pairs never straddle levels. Final shfl_xor(16) merges the
// two half-warp partials; lanes 0-15 store float2.
// SOAW row layout: [so (256) | aw logits (128)]  stride 384.
// ---------------------------------------------------------------------------
__global__ __launch_bounds__(256) void sample_kernel(
    const float* __restrict__ ref,    // [B, LQ, 4, 2]
    const float* __restrict__ v,      // [B, LV, H, HD]
    const float* __restrict__ soaw,   // [B*LQ, 384]
    float* __restrict__ acc_out)      // [B*LQ, 256]
{
    const int w    = blockIdx.x * 8 + (threadIdx.x >> 5);
    const int lane = threadIdx.x & 31;
    const int h    = w & 7;
    const int bq   = w >> 3;
    const int b    = bq >> 10;

    const int half = lane >> 4;        // 0 or 1: which point of the pair
    const int ch   = (lane & 15) * 2;  // channel pair

    const float*  row  = soaw + (size_t)bq * 384;
    const float2* so2  = (const float2*)(row + h * 32);   // 16 offset pairs
    const float*  aw_p = row + 256 + h * 16;
    const float*  ref_p = ref + (size_t)bq * 8;
    const float*  vb   = v + (size_t)b * cfg::LV * cfg::D + h * 32 + ch;

    // In-warp softmax over 16 logits (xor reductions within 16-lane halves)
    float logit = (lane < 16) ? aw_p[lane] : -1e30f;
    float mx = logit;
#pragma unroll
    for (int off = 8; off >= 1; off >>= 1)
        mx = fmaxf(mx, __shfl_xor_sync(0xffffffffu, mx, off));
    float e = __expf(logit - mx);
    float ssum = e;
#pragma unroll
    for (int off = 8; off >= 1; off >>= 1)
        ssum += __shfl_xor_sync(0xffffffffu, ssum, off);
    const float wnorm = e / ssum;     // valid on lanes 0..15

    const int LHW[4]    = {100, 50, 25, 13};
    const int LSTART[4] = {0, 10000, 12500, 13125};

    float2 acc2 = make_float2(0.f, 0.f);
#pragma unroll
    for (int l = 0; l < 4; l++) {
        const int   Wl = LHW[l];
        const int   Hl = LHW[l];
        const float bx = ref_p[l * 2 + 0] * (float)Wl - 0.5f;
        const float by = ref_p[l * 2 + 1] * (float)Hl - 0.5f;
        const float* base = vb + (size_t)LSTART[l] * cfg::D;

#pragma unroll
        for (int pp = 0; pp < 2; pp++) {
            const int   idx = l * 4 + pp * 2 + half;     // my point 0..15
            const float2 so = so2[idx];
            const float x   = bx + so.x;
            const float y   = by + so.y;
            const float wt  = __shfl_sync(0xffffffffu, wnorm, idx);

            const float x0f = floorf(x), y0f = floorf(y);
            const int   ix0 = (int)x0f,  iy0 = (int)y0f;
            const float fx = x - x0f,    fy = y - y0f;

            const bool vx0 = (ix0 >= 0)     && (ix0 < Wl);
            const bool vx1 = (ix0 + 1 >= 0) && (ix0 + 1 < Wl);
            const bool vy0 = (iy0 >= 0)     && (iy0 < Hl);
            const bool vy1 = (iy0 + 1 >= 0) && (iy0 + 1 < Hl);

            float2 v00 = make_float2(0.f, 0.f), v01 = v00;
            float2 v10 = v00, v11 = v00;
            if (vy0) {
                const float* r0 = base + (size_t)(iy0 * Wl) * cfg::D;
                if (vx0) v01 = v00 = *(const float2*)(r0 + (size_t)ix0 * cfg::D),
                         v01 = v00;
                if (vx0) v00 = *(const float2*)(r0 + (size_t)ix0 * cfg::D);
                else     v00 = make_float2(0.f, 0.f);
                if (vx1) v01 = *(const float2*)(r0 + (size_t)(ix0 + 1) * cfg::D);
                else     v01 = make_float2(0.f, 0.f);
            }
            if (vy1) {
                const float* r1 = base + (size_t)((iy0 + 1) * Wl) * cfg::D;
                if (vx0) v10 = *(const float2*)(r1 + (size_t)ix0 * cfg::D);
                if (vx1) v11 = *(const float2*)(r1 + (size_t)(ix0 + 1) * cfg::D);
            }

            const float w00 = (1.f - fx) * (1.f - fy);
            const float w01 = fx * (1.f - fy);
            const float w10 = (1.f - fx) * fy;
            const float w11 = fx * fy;

            acc2.x = fmaf(wt, v00.x * w00 + v01.x * w01 +
                              v10.x * w10 + v11.x * w11, acc2.x);
            acc2.y = fmaf(wt, v00.y * w00 + v01.y * w01 +
                              v10.y * w10 + v11.y * w11, acc2.y);
        }
    }

    // Merge the two half-warp partials (channels identical across halves)
    acc2.x += __shfl_xor_sync(0xffffffffu, acc2.x, 16);
    acc2.y += __shfl_xor_sync(0xffffffffu, acc2.y, 16);
    if (lane < 16)
        *(float2*)(acc_out + (size_t)bq * 256 + h * 32 + ch) = acc2;
}

// ---------------------------------------------------------------------------
// Launch
// ---------------------------------------------------------------------------
extern "C" void kernel_launch(void* const* d_in, const int* in_sizes, int n_in,
                              void* d_out, int out_size)
{
    const float* query = (const float*)d_in[0];   // [8,1024,256]
    const float* refp  = (const float*)d_in[1];   // [8,1024,4,2]
    const float* value = (const float*)d_in[2];   // [8,13294,256]
    // d_in[3] = value_spatial_shapes (compile-time constant)
    const float* so_w  = (const float*)d_in[4];   // [256,256]  [K,N]
    const float* so_b  = (const float*)d_in[5];
    const float* aw_w  = (const float*)d_in[6];   // [256,128]  [K,N]
    const float* aw_b  = (const float*)d_in[7];
    const float* vp_w  = (const float*)d_in[8];   // [256,256]  [K,N]
    const float* vp_b  = (const float*)d_in[9];
    const float* op_w  = (const float*)d_in[10];  // [256,256]  [K,N]
    const float* op_b  = (const float*)d_in[11];
    float* out = (float*)d_out;                   // [8,1024,256]

    float* scratch = nullptr;
    cudaGetSymbolAddress((void**)&scratch, g_scratch);
    float* sV    = scratch + cfg::OFF_V;
    float* sSOAW = scratch + cfg::OFF_SOAW;
    float* sACC  = scratch + cfg::OFF_ACC;

    const int MQ = cfg::B * cfg::LQ;      // 8192
    const int MV = cfg::B * cfg::LV;      // 106352

    // 1) v = value @ vp_w + vp_b
    tf32_gemm_dual<<<dim3(2, (MV + 127) / 128), 256>>>(
        value, vp_w, 256, vp_w, 256, 256, vp_b, vp_b, sV, MV, 256, 256);
    // 2) soaw = query @ [so_w | aw_w] + [so_b | aw_b]  (split at col 256)
    tf32_gemm_dual<<<dim3(3, MQ / 128), 256>>>(
        query, so_w, 256, aw_w, 128, 256, so_b, aw_b, sSOAW, MQ, 384, 256);
    // 3) sampling (softmax folded in; 2 points per warp, float2 lanes)
    {
        int warps = cfg::B * cfg::LQ * cfg::H;   // 65536
        sample_kernel<<<warps / 8, 256>>>(refp, sV, sSOAW, sACC);
    }
    // 4) out = ACC @ op_w + op_b
    tf32_gemm_dual<<<dim3(2, MQ / 128), 256>>>(
        sACC, op_w, 256, op_w, 256, 256, op_b, op_b, out, MQ, 256, 256);
}